// round 8
// baseline (speedup 1.0000x reference)
#include <cuda_runtime.h>
#include <math_constants.h>

// Problem constants (fixed by setup_inputs)
#define BS   32
#define C    128
#define GN   256
#define S    16
#define G    (BS * GN)      // 8192 groups
#define NG   2              // groups per block (consecutive gn -> memory adjacent)
#define NB   (G / NG)       // 4096 blocks
#define NT   512            // threads per block
#define MAXN 9              // bg + up to 8 fg instances (labels in [-1,8))
#define INVT 5.0f           // 1 / T, T = 0.2
#define WLOSS 0.1f

__device__ float2   g_part[G];   // per-group (gl*gv, gv)
__device__ unsigned g_ctr = 0;   // completed-block counter (self-resetting)

__global__ __launch_bounds__(NT, 3)
void fused_kernel(const int*   __restrict__ lab_g,   // [bs, Gn, S]
                  const float* __restrict__ feat_g,  // [bs, C, Gn, S]
                  const int*   __restrict__ idx_g,   // [bs, Gn, S]
                  const float* __restrict__ ctx,     // [1, C]
                  float*       __restrict__ out)
{
    __shared__ __align__(16) float4 st4[C][8];          // staged tile, XOR-swizzled, 16KB
    __shared__ __align__(16) float  Mrow[NG][MAXN][C];  // instance means, 9KB
    __shared__ float2 ss2[NG][S];                       // (scale, slot-as-float)
    __shared__ int    instNum[NG];
    __shared__ int    hasBg[NG];
    __shared__ float  liPart[NG][8];
    __shared__ int    sIsLast;
    __shared__ float  red[32];

    const int t   = threadIdx.x;
    const int g0  = blockIdx.x * NG;
    const int b   = g0 / GN;
    const int gn0 = g0 % GN;

    // ---------------- Phase 0: async coalesced gmem -> smem staging ----------------
    {
        const float4* src = (const float4*)(feat_g + ((size_t)b * C * GN + gn0) * S);
        unsigned sbase = (unsigned)__cvta_generic_to_shared(&st4[0][0]);
        #pragma unroll
        for (int it = 0; it < 2; ++it) {
            int f4 = t + it * NT;           // 0..1023
            int c  = f4 >> 3;
            int k  = f4 & 7;
            unsigned dst = sbase + (unsigned)((c * 8 + (k ^ (c & 7))) * 16);
            const void* gp = (const void*)(src + (size_t)c * (GN * S / 4) + k);
            asm volatile("cp.async.cg.shared.global [%0], [%1], 16;" :: "r"(dst), "l"(gp));
        }
        asm volatile("cp.async.commit_group;");
    }

    // ---------------- Phase 1: warp-parallel slot metadata (warps 0,1) ----------------
    if (t < 64) {
        const int  w    = t >> 5;           // local group
        const int  lane = t & 31;
        const int  grp  = g0 + w;
        const bool sm   = lane < S;
        // lanes >= S carry unique sentinels so they never match real values
        int myIdx = sm ? idx_g[(size_t)grp * S + lane] : (0x40000000 | lane);
        int myLab = sm ? lab_g[(size_t)grp * S + lane] : 0;
        unsigned mi    = __match_any_sync(0xffffffffu, myIdx);
        bool     leadI = sm && (lane == (__ffs(mi) - 1));
        int      u     = __popc(__ballot_sync(0xffffffffu, leadI));   // distinct seed idx count
        bool     valid = sm && (lane < u);
        int      labm  = valid ? myLab : (0x41000000 | lane);
        unsigned ml    = __match_any_sync(0xffffffffu, labm);
        bool     isBg  = valid && (myLab < 0);
        bool     isFg  = valid && (myLab >= 0);
        int      leadLane = __ffs(ml) - 1;
        unsigned fgLead   = __ballot_sync(0xffffffffu, isFg && (lane == leadLane));
        unsigned bgB      = __ballot_sync(0xffffffffu, isBg);
        int      nfg      = __popc(fgLead);
        int   slot  = -1;
        float scale = 0.0f;
        if (valid) {
            scale = 1.0f / (float)__popc(ml);   // ml only holds matching (valid) lanes
            slot  = isBg ? 0 : (1 + __popc(fgLead & ((1u << leadLane) - 1u)));
        }
        if (sm) ss2[w][lane] = make_float2(scale, __int_as_float(slot));
        if (lane == 0) { instNum[w] = nfg + 1; hasBg[w] = (bgB != 0); }
    }
    asm volatile("cp.async.wait_group 0;");
    __syncthreads();

    // ---------------- Phase 2: per-instance means, register accumulators ----------------
    // Thread (gl, c) owns one channel column; slots resolved by predication (no smem RMW).
    if (t < 256) {
        const int gl = t >> 7;
        const int c  = t & 127;
        float acc[MAXN];
        #pragma unroll
        for (int k = 0; k < MAXN; ++k) acc[k] = 0.0f;
        #pragma unroll
        for (int q = 0; q < 4; ++q) {
            float4 fv = st4[c][(gl * 4 + q) ^ (c & 7)];
            float fq[4] = {fv.x, fv.y, fv.z, fv.w};
            #pragma unroll
            for (int u4 = 0; u4 < 4; ++u4) {
                float2 sv = ss2[gl][q * 4 + u4];
                int    sl = __float_as_int(sv.y);
                float  v  = fq[u4] * sv.x;
                #pragma unroll
                for (int k = 0; k < MAXN; ++k)
                    if (sl == k) acc[k] += v;     // independent predicated adds
            }
        }
        #pragma unroll
        for (int k = 0; k < MAXN; ++k) Mrow[gl][k][c] = acc[k];
        if (!hasBg[gl]) Mrow[gl][0][c] = __ldg(ctx + c);
    }
    __syncthreads();

    // ---------------- Phase 3: sim row + logsumexp (one fg row per warp) ----------------
    {
        const int w    = t >> 5;       // 0..15
        const int lane = t & 31;
        const int gl   = w >> 3;
        const int r    = w & 7;
        const int n    = instNum[gl];
        const int i1   = 1 + r;
        float li = 0.0f;
        if (i1 < n) {
            const float4* Mv = (const float4*)&Mrow[gl][0][0];   // 32 float4 per row
            float4 a1 = Mv[i1 * 32 + lane];
            float p[MAXN];
            #pragma unroll
            for (int j = 0; j < MAXN; ++j) {
                float4 bb = Mv[j * 32 + lane];   // unused slots are zero: safe
                p[j] = a1.x*bb.x + a1.y*bb.y + a1.z*bb.z + a1.w*bb.w;
            }
            // stage-parallel butterfly: 9 independent chains -> high ILP
            #pragma unroll
            for (int o = 16; o > 0; o >>= 1) {
                #pragma unroll
                for (int j = 0; j < MAXN; ++j)
                    p[j] += __shfl_xor_sync(0xffffffffu, p[j], o);
            }
            // lse fully in registers (replicated across lanes, shfl-free)
            float m = -CUDART_INF_F;
            #pragma unroll
            for (int j = 0; j < MAXN; ++j) {
                p[j] = (j < n) ? p[j] * INVT : -CUDART_INF_F;
                m = fmaxf(m, p[j]);
            }
            float ssum = 0.f, diag = 0.f;
            #pragma unroll
            for (int j = 0; j < MAXN; ++j) {
                ssum += __expf(p[j] - m);
                if (j == i1) diag = p[j];
            }
            li = m + __logf(ssum) - diag;
        }
        if (lane == 0) liPart[gl][r] = li;
    }
    __syncthreads();

    // ---------------- Phase 4: per-group loss + completion signal ----------------
    if (t == 0) {
        #pragma unroll
        for (int gl = 0; gl < NG; ++gl) {
            float ls = 0.0f;
            #pragma unroll
            for (int r = 0; r < 8; ++r) ls += liPart[gl][r];
            int   fg    = instNum[gl] - 1;
            float valid = (fg >= 1) ? 1.0f : 0.0f;
            float glv   = (fg >= 1) ? (ls / (float)fg) : 0.0f;
            g_part[g0 + gl] = make_float2(glv * valid, valid);
        }
        __threadfence();                       // publish g_part before signaling
        unsigned o = atomicAdd(&g_ctr, 1u);
        sIsLast = (o == (unsigned)(NB - 1));
    }
    __syncthreads();

    // ---------------- Phase 5: last block performs the (deterministic) final reduce ----------------
    if (sIsLast) {
        if (t == 0) __threadfence();           // acquire all g_part writes
        __syncthreads();
        const float4* gp = (const float4*)g_part;   // G/2 float4
        float ax = 0.0f, ay = 0.0f;
        #pragma unroll 4
        for (int i = t; i < G / 2; i += NT) {
            float4 v = gp[i];
            ax += v.x + v.z;
            ay += v.y + v.w;
        }
        #pragma unroll
        for (int o = 16; o > 0; o >>= 1) {
            ax += __shfl_xor_sync(0xffffffffu, ax, o);
            ay += __shfl_xor_sync(0xffffffffu, ay, o);
        }
        if ((t & 31) == 0) { red[t >> 5] = ax; red[16 + (t >> 5)] = ay; }
        __syncthreads();
        if (t == 0) {
            float sx = 0.f, sy = 0.f;
            #pragma unroll
            for (int q = 0; q < 16; ++q) { sx += red[q]; sy += red[16 + q]; }
            out[0] = sx / sy * WLOSS;
            atomicExch(&g_ctr, 0u);            // visible reset for next graph replay
        }
    }
}

extern "C" void kernel_launch(void* const* d_in, const int* in_sizes, int n_in,
                              void* d_out, int out_size)
{
    const int*   lab  = (const int*)  d_in[0];   // proposal_instance_mask
    const float* feat = (const float*)d_in[1];   // grouped_features
    const int*   idx  = (const int*)  d_in[2];   // grouped_indices
    const float* ctx  = (const float*)d_in[3];   // context_compen
    (void)in_sizes; (void)n_in; (void)out_size;

    fused_kernel<<<NB, NT>>>(lab, feat, idx, ctx, (float*)d_out);
}

// round 9
// speedup vs baseline: 1.2410x; 1.2410x over previous
#include <cuda_runtime.h>
#include <math_constants.h>

// Problem constants (fixed by setup_inputs)
#define BS     32
#define C      128
#define GN     256
#define S      16
#define NTILES 4096          // G / NG
#define NG     2             // groups per tile (consecutive gn -> memory adjacent)
#define NBLK   592           // 4 blocks per SM on 148 SMs, persistent
#define NT     256
#define MAXN   9             // bg + up to 8 fg instances (labels in [-1,8))
#define INVT   5.0f          // 1 / T, T = 0.2
#define WLOSS  0.1f

__device__ float2   g_part[NBLK];   // per-block (sum gl*gv, sum gv)
__device__ unsigned g_ctr = 0;      // completed-block counter (self-resetting)

__global__ __launch_bounds__(NT, 4)
void fused_kernel(const int*   __restrict__ lab_g,   // [bs, Gn, S]
                  const float* __restrict__ feat_g,  // [bs, C, Gn, S]
                  const int*   __restrict__ idx_g,   // [bs, Gn, S]
                  const float* __restrict__ ctx,     // [1, C]
                  float*       __restrict__ out)
{
    __shared__ __align__(16) float4 st4[2][C][8];       // double-buffered tile, 32KB
    __shared__ __align__(16) float  Mrow[NG][MAXN][C];  // instance means, 9KB
    __shared__ float2 ss2[NG][S];                       // (scale, slot-as-float)
    __shared__ int    instNum[NG];
    __shared__ int    hasBg[NG];
    __shared__ float  liPart[NG][4];
    __shared__ int    sIsLast;
    __shared__ float  red[16];

    const int t    = threadIdx.x;
    const int lane = t & 31;
    const unsigned sb0 = (unsigned)__cvta_generic_to_shared(&st4[0][0][0]);
    const int   c2   = t & 127;                 // phase-2 channel
    const int   gl2  = t >> 7;                  // phase-2 local group
    const float ctxv = __ldg(ctx + c2);

    int   tile = blockIdx.x;
    int   buf  = 0;
    float ax = 0.0f, ay = 0.0f;                 // per-block loss accumulators (t==0)
    int   pIdx = 0, pLab = 0;                   // prefetched metadata (warps 0,1)

    // ---------------- prologue: stage first tile + its metadata ----------------
    {
        const int g0 = tile * NG, b = g0 / GN, gn0 = g0 % GN;
        const float4* src = (const float4*)(feat_g + ((size_t)b * C * GN + gn0) * S);
        #pragma unroll
        for (int q = 0; q < 4; ++q) {
            int f4 = t + q * NT;                // 0..1023
            int c  = f4 >> 3, k = f4 & 7;
            unsigned dst = sb0 + (unsigned)((c * 8 + (k ^ (c & 7))) * 16);
            const void* gp = (const void*)(src + (size_t)c * (GN * S / 4) + k);
            asm volatile("cp.async.cg.shared.global [%0], [%1], 16;" :: "r"(dst), "l"(gp));
        }
        asm volatile("cp.async.commit_group;");
        if (t < 64 && lane < S) {
            int grp = g0 + (t >> 5);
            pIdx = idx_g[(size_t)grp * S + lane];
            pLab = lab_g[(size_t)grp * S + lane];
        }
    }

    // ---------------- persistent tile loop (double-buffered) ----------------
    for (; tile < NTILES; tile += NBLK) {
        const int  nextTile = tile + NBLK;
        const bool hasNext  = nextTile < NTILES;

        // issue prefetch of next tile into the other buffer
        if (hasNext) {
            const int g0n = nextTile * NG, bn = g0n / GN, gn0n = g0n % GN;
            const float4* src = (const float4*)(feat_g + ((size_t)bn * C * GN + gn0n) * S);
            const unsigned sb = sb0 + (unsigned)((buf ^ 1) * (C * 8 * 16));
            #pragma unroll
            for (int q = 0; q < 4; ++q) {
                int f4 = t + q * NT;
                int c  = f4 >> 3, k = f4 & 7;
                unsigned dst = sb + (unsigned)((c * 8 + (k ^ (c & 7))) * 16);
                const void* gp = (const void*)(src + (size_t)c * (GN * S / 4) + k);
                asm volatile("cp.async.cg.shared.global [%0], [%1], 16;" :: "r"(dst), "l"(gp));
            }
            asm volatile("cp.async.commit_group;");
        }

        // phase 1: warp-parallel slot metadata for current tile (warps 0,1)
        if (t < 64) {
            const int  w  = t >> 5;
            const bool sm = lane < S;
            int myIdx = sm ? pIdx : (0x40000000 | lane);   // unique sentinels on lanes >= S
            int myLab = sm ? pLab : 0;
            unsigned mi    = __match_any_sync(0xffffffffu, myIdx);
            bool     leadI = sm && (lane == (__ffs(mi) - 1));
            int      u     = __popc(__ballot_sync(0xffffffffu, leadI));  // distinct seed idx count
            bool     valid = sm && (lane < u);
            int      labm  = valid ? myLab : (0x41000000 | lane);
            unsigned ml    = __match_any_sync(0xffffffffu, labm);
            bool     isBg  = valid && (myLab < 0);
            bool     isFg  = valid && (myLab >= 0);
            int      leadLane = __ffs(ml) - 1;
            unsigned fgLead   = __ballot_sync(0xffffffffu, isFg && (lane == leadLane));
            unsigned bgB      = __ballot_sync(0xffffffffu, isBg);
            int      nfg      = __popc(fgLead);
            int   slot  = -1;
            float scale = 0.0f;
            if (valid) {
                scale = 1.0f / (float)__popc(ml);
                slot  = isBg ? 0 : (1 + __popc(fgLead & ((1u << leadLane) - 1u)));
            }
            if (sm) ss2[w][lane] = make_float2(scale, __int_as_float(slot));
            if (lane == 0) { instNum[w] = nfg + 1; hasBg[w] = (bgB != 0); }
            // prefetch next tile's metadata (lands during phases 2-3)
            if (hasNext && sm) {
                int grpN = nextTile * NG + w;
                pIdx = idx_g[(size_t)grpN * S + lane];
                pLab = lab_g[(size_t)grpN * S + lane];
            }
        }
        if (hasNext) asm volatile("cp.async.wait_group 1;");   // current tile resident
        else         asm volatile("cp.async.wait_group 0;");
        __syncthreads();                                       // B1

        // phase 2: per-instance means, register accumulators (all 256 threads)
        {
            float acc[MAXN];
            #pragma unroll
            for (int k = 0; k < MAXN; ++k) acc[k] = 0.0f;
            const float4 (*stb)[8] = st4[buf];
            #pragma unroll
            for (int q = 0; q < 4; ++q) {
                float4 fv = stb[c2][(gl2 * 4 + q) ^ (c2 & 7)];
                float fq[4] = {fv.x, fv.y, fv.z, fv.w};
                #pragma unroll
                for (int u4 = 0; u4 < 4; ++u4) {
                    float2 sv = ss2[gl2][q * 4 + u4];
                    int    sl = __float_as_int(sv.y);
                    float  v  = fq[u4] * sv.x;
                    #pragma unroll
                    for (int k = 0; k < MAXN; ++k)
                        if (sl == k) acc[k] += v;      // independent predicated adds
                }
            }
            #pragma unroll
            for (int k = 0; k < MAXN; ++k) Mrow[gl2][k][c2] = acc[k];
            if (!hasBg[gl2]) Mrow[gl2][0][c2] = ctxv;
        }
        __syncthreads();                                       // B2

        // phase 3: sim rows + logsumexp (warp = 2 fg rows)
        {
            const int w   = t >> 5;        // 0..7
            const int glw = w >> 2;
            const int r   = w & 3;
            const int n   = instNum[glw];
            const int i1  = 1 + r;
            const int i2  = 5 + r;
            float li = 0.0f;
            if (i1 < n) {
                const float4* Mv = (const float4*)&Mrow[glw][0][0];   // 32 float4 per row
                float4 a1 = Mv[i1 * 32 + lane];
                const bool v2 = (i2 < n);
                float4 a2 = v2 ? Mv[i2 * 32 + lane] : make_float4(0.f,0.f,0.f,0.f);
                float p1[MAXN], p2[MAXN];
                #pragma unroll
                for (int j = 0; j < MAXN; ++j) {
                    float4 bb = Mv[j * 32 + lane];    // rows >= n are zeroed: safe
                    p1[j] = a1.x*bb.x + a1.y*bb.y + a1.z*bb.z + a1.w*bb.w;
                    p2[j] = a2.x*bb.x + a2.y*bb.y + a2.z*bb.z + a2.w*bb.w;
                }
                #pragma unroll
                for (int o = 16; o > 0; o >>= 1) {    // 18 independent chains -> high ILP
                    #pragma unroll
                    for (int j = 0; j < MAXN; ++j) {
                        p1[j] += __shfl_xor_sync(0xffffffffu, p1[j], o);
                        p2[j] += __shfl_xor_sync(0xffffffffu, p2[j], o);
                    }
                }
                float m1 = -CUDART_INF_F, m2 = -CUDART_INF_F;
                #pragma unroll
                for (int j = 0; j < MAXN; ++j) {
                    p1[j] = (j < n) ? p1[j] * INVT : -CUDART_INF_F;
                    p2[j] = (j < n) ? p2[j] * INVT : -CUDART_INF_F;
                    m1 = fmaxf(m1, p1[j]);
                    m2 = fmaxf(m2, p2[j]);
                }
                float s1 = 0.f, s2 = 0.f, d1 = 0.f, d2 = 0.f;
                #pragma unroll
                for (int j = 0; j < MAXN; ++j) {
                    s1 += __expf(p1[j] - m1);
                    s2 += __expf(p2[j] - m2);
                    if (j == i1) d1 = p1[j];
                    if (j == i2) d2 = p2[j];
                }
                li = m1 + __logf(s1) - d1;
                if (v2) li += m2 + __logf(s2) - d2;
            }
            if (lane == 0) liPart[glw][r] = li;
        }
        __syncthreads();                                       // B3

        // per-tile loss -> register accumulators
        if (t == 0) {
            #pragma unroll
            for (int gl = 0; gl < NG; ++gl) {
                float ls = liPart[gl][0] + liPart[gl][1] + liPart[gl][2] + liPart[gl][3];
                int   fg = instNum[gl] - 1;
                if (fg >= 1) { ax += ls / (float)fg; ay += 1.0f; }
            }
        }
        buf ^= 1;
    }

    // ---------------- epilogue: one write + one atomic per block ----------------
    if (t == 0) {
        g_part[blockIdx.x] = make_float2(ax, ay);
        __threadfence();                          // publish before signaling
        unsigned o = atomicAdd(&g_ctr, 1u);
        sIsLast = (o == (unsigned)(NBLK - 1));
    }
    __syncthreads();

    if (sIsLast) {
        if (t == 0) __threadfence();              // acquire all g_part writes
        __syncthreads();
        float sx = 0.f, sy = 0.f;
        for (int i = t; i < NBLK; i += NT) {
            float2 v = g_part[i];
            sx += v.x; sy += v.y;
        }
        #pragma unroll
        for (int o = 16; o > 0; o >>= 1) {
            sx += __shfl_xor_sync(0xffffffffu, sx, o);
            sy += __shfl_xor_sync(0xffffffffu, sy, o);
        }
        if (lane == 0) { red[t >> 5] = sx; red[8 + (t >> 5)] = sy; }
        __syncthreads();
        if (t == 0) {
            float fx = 0.f, fy = 0.f;
            #pragma unroll
            for (int q = 0; q < 8; ++q) { fx += red[q]; fy += red[8 + q]; }
            out[0] = fx / fy * WLOSS;
            atomicExch(&g_ctr, 0u);               // visible reset for next graph replay
        }
    }
}

extern "C" void kernel_launch(void* const* d_in, const int* in_sizes, int n_in,
                              void* d_out, int out_size)
{
    const int*   lab  = (const int*)  d_in[0];   // proposal_instance_mask
    const float* feat = (const float*)d_in[1];   // grouped_features
    const int*   idx  = (const int*)  d_in[2];   // grouped_indices
    const float* ctx  = (const float*)d_in[3];   // context_compen
    (void)in_sizes; (void)n_in; (void)out_size;

    fused_kernel<<<NBLK, NT>>>(lab, feat, idx, ctx, (float*)d_out);
}